// round 16
// baseline (speedup 1.0000x reference)
#include <cuda_runtime.h>
#include <cuda_bf16.h>
#include <math_constants.h>
#include <cstdint>

#define B_  64
#define T_  1380
#define T2  (T_/2)      // 690 bf16 pairs per L row
#define TP  1408        // T padded to multiple of 32
#define TP2 (TP/2)      // 704 packed pairs
#define XD  96
#define XP2 (XD/2)      // 48
#define HD  192
#define HP2 (HD/2)      // 96
#define CN  345
#define CAPG 1408       // per-row candidate capacity (>= T: cannot overflow)

#define THR_LN   18.421f   // -ln(1e-8)
#define SLACK    2.0f      // covers bf16-product + bf16-storage logit error (bound ~1.2)

// ---------------------------------------------------------------------------
// Scratch (device globals). hi/lo bf16 pairs packed in uint32 (low = lower k).
// ---------------------------------------------------------------------------
__device__ uint32_t g_W2h[(size_t)CN * TP2],      g_W2l[(size_t)CN * TP2];
__device__ uint32_t g_Xth[(size_t)B_ * XD * TP2], g_Xtl[(size_t)B_ * XD * TP2];
__device__ uint32_t g_W1th[(size_t)HD * XP2],     g_W1tl[(size_t)HD * XP2];
__device__ uint32_t g_Hh [(size_t)B_ * T_ * HP2];
__device__ uint32_t g_Zh [(size_t)B_ * CN * XP2], g_Zl [(size_t)B_ * CN * XP2];
__device__ uint32_t g_Yh [(size_t)B_ * CN * HP2], g_Yl [(size_t)B_ * CN * HP2];
__device__ uint32_t g_Lb [(size_t)B_ * CN * T2];   // bf16x2 packed logits
__device__ uint32_t g_CI [(size_t)B_ * CN * CAPG]; // candidate indices
__device__ float    g_CL [(size_t)B_ * CN * CAPG]; // candidate logits / probs

// ---------------------------------------------------------------------------
// Helpers
// ---------------------------------------------------------------------------
__device__ __forceinline__ uint32_t enc_f(float f) {
    uint32_t u = __float_as_uint(f);
    return (u & 0x80000000u) ? ~u : (u | 0x80000000u);
}
__device__ __forceinline__ float dec_f(uint32_t k) {
    uint32_t u = (k & 0x80000000u) ? (k ^ 0x80000000u) : ~k;
    return __uint_as_float(u);
}

__device__ __forceinline__ void split_pair(float x0, float x1,
                                           uint32_t& hi, uint32_t& lo) {
    __nv_bfloat16 h0 = __float2bfloat16_rn(x0);
    __nv_bfloat16 h1 = __float2bfloat16_rn(x1);
    float r0 = x0 - __bfloat162float(h0);
    float r1 = x1 - __bfloat162float(h1);
    __nv_bfloat16 l0 = __float2bfloat16_rn(r0);
    __nv_bfloat16 l1 = __float2bfloat16_rn(r1);
    hi = ((uint32_t)__bfloat16_as_ushort(h1) << 16) | __bfloat16_as_ushort(h0);
    lo = ((uint32_t)__bfloat16_as_ushort(l1) << 16) | __bfloat16_as_ushort(l0);
}

__device__ __forceinline__ float bf_lo(uint32_t u) {
    return __bfloat162float(__ushort_as_bfloat16((unsigned short)(u & 0xffffu)));
}
__device__ __forceinline__ float bf_hi(uint32_t u) {
    return __bfloat162float(__ushort_as_bfloat16((unsigned short)(u >> 16)));
}

__device__ __forceinline__ void mma_bf16(float* c, const uint32_t* a, const uint32_t* b) {
    asm volatile(
        "mma.sync.aligned.m16n8k16.row.col.f32.bf16.bf16.f32 "
        "{%0,%1,%2,%3}, {%4,%5,%6,%7}, {%8,%9}, {%0,%1,%2,%3};"
        : "+f"(c[0]), "+f"(c[1]), "+f"(c[2]), "+f"(c[3])
        : "r"(a[0]), "r"(a[1]), "r"(a[2]), "r"(a[3]),
          "r"(b[0]), "r"(b[1]));
}

__device__ __forceinline__ void ldsm4(uint32_t* r, uint32_t saddr) {
    asm volatile("ldmatrix.sync.aligned.m8n8.x4.shared.b16 {%0,%1,%2,%3}, [%4];"
                 : "=r"(r[0]), "=r"(r[1]), "=r"(r[2]), "=r"(r[3]) : "r"(saddr));
}

__device__ __forceinline__ void cp16(uint32_t dst, const void* src, bool ok) {
    asm volatile(
        "{\n\t.reg .pred p;\n\t.reg .b32 sz;\n\t"
        "setp.ne.u32 p, %2, 0;\n\t"
        "selp.b32 sz, 16, 0, p;\n\t"
        "cp.async.cg.shared.global [%0], [%1], 16, sz;\n\t}"
        :: "r"(dst), "l"(src), "r"((uint32_t)ok) : "memory");
}
#define CP_COMMIT() asm volatile("cp.async.commit_group;" ::: "memory")

// ---------------------------------------------------------------------------
// Prepass kernels
// ---------------------------------------------------------------------------
__global__ void split_pack(const float* __restrict__ src,
                           uint32_t* __restrict__ dh, uint32_t* __restrict__ dl,
                           int rows, int C, int Cp2) {
    size_t idx = (size_t)blockIdx.x * 256 + threadIdx.x;
    size_t total = (size_t)rows * Cp2;
    if (idx >= total) return;
    int r = (int)(idx / Cp2);
    int j = (int)(idx - (size_t)r * Cp2);
    float2 v = make_float2(0.f, 0.f);
    if (2 * j < C)
        v = *reinterpret_cast<const float2*>(src + (size_t)r * C + 2 * j);
    uint32_t hi, lo;
    split_pair(v.x, v.y, hi, lo);
    dh[idx] = hi;
    dl[idx] = lo;
}

__global__ void pack_hi(const float* __restrict__ src,
                        uint32_t* __restrict__ dh, int rows, int C, int Cp2) {
    size_t idx = (size_t)blockIdx.x * 256 + threadIdx.x;
    size_t total = (size_t)rows * Cp2;
    if (idx >= total) return;
    int r = (int)(idx / Cp2);
    int j = (int)(idx - (size_t)r * Cp2);
    float2 v = make_float2(0.f, 0.f);
    if (2 * j < C)
        v = *reinterpret_cast<const float2*>(src + (size_t)r * C + 2 * j);
    __nv_bfloat16 h0 = __float2bfloat16_rn(v.x);
    __nv_bfloat16 h1 = __float2bfloat16_rn(v.y);
    dh[idx] = ((uint32_t)__bfloat16_as_ushort(h1) << 16) | __bfloat16_as_ushort(h0);
}

__global__ void split_transpose(const float* __restrict__ src, size_t sSrc,
                                uint32_t* __restrict__ dh, uint32_t* __restrict__ dl,
                                size_t sDst, int R, int C, int Rp2) {
    __shared__ float t[32][33];
    const int b = blockIdx.z;
    src += sSrc * b;
    dh  += sDst * b;
    dl  += sDst * b;
    const int r0 = blockIdx.x * 32;
    const int c0 = blockIdx.y * 32;
    const int tx = threadIdx.x, ty = threadIdx.y;

    #pragma unroll
    for (int i = 0; i < 4; i++) {
        int r = r0 + ty + i * 8, c = c0 + tx;
        t[ty + i * 8][tx] = (r < R && c < C) ? src[(size_t)r * C + c] : 0.f;
    }
    __syncthreads();
    if (tx < 16) {
        #pragma unroll
        for (int i = 0; i < 4; i++) {
            int cc = ty + i * 8, c = c0 + cc;
            if (c < C) {
                uint32_t hi, lo;
                split_pair(t[2 * tx][cc], t[2 * tx + 1][cc], hi, lo);
                size_t o = (size_t)c * Rp2 + (r0 >> 1) + tx;
                dh[o] = hi;
                dl[o] = lo;
            }
        }
    }
}

// ---------------------------------------------------------------------------
// Split-compensated bf16 GEMM for steps 1 & 2.
// ---------------------------------------------------------------------------
template<int BN>
__global__ __launch_bounds__(256, 2)
void gemm_bf16s(const uint32_t* __restrict__ Ah, const uint32_t* __restrict__ Al, size_t sA,
                const uint32_t* __restrict__ Bh, const uint32_t* __restrict__ Bl, size_t sB,
                uint32_t* __restrict__ Ch, uint32_t* __restrict__ Cl,
                size_t sC, int M, int N, int Kp, float alpha)
{
    constexpr int NI = BN / 16;
    constexpr int PR = BN / 32;
    constexpr int A_U32 = 4096;
    constexpr int B_OFF = A_U32;
    constexpr int B_U32 = BN * 32;
    constexpr int STG_U32 = A_U32 + B_U32;
    constexpr int STG_B = STG_U32 * 4;
    constexpr int NSTAGE = 4;
    constexpr int TA = 1024;
    constexpr int TB = BN * 8;

    extern __shared__ uint32_t sm[];
    const uint32_t sbase = (uint32_t)__cvta_generic_to_shared(sm);

    const int b = blockIdx.z;
    Ah += sA * b;  Al += sA * b;
    Bh += sB * b;  Bl += sB * b;
    const int m0 = blockIdx.x * 128;
    const int n0 = blockIdx.y * BN;
    const int tid  = threadIdx.x;
    const int warp = tid >> 5, lane = tid & 31;
    const int wm = warp >> 1, wn = warp & 1;
    const int l4 = lane >> 2, lk = lane & 3;
    const int Kp2 = Kp >> 1;

    const int lt = lane >> 3, lr = lane & 7;
    const int rowA = (lt & 1) * 8 + lr;
    const int gA   = lt >> 1;
    const int rowB = (lt >> 1) * 8 + lr;
    const int gB   = lt & 1;

    uint32_t aAddr[2], bAddr[PR];
    #pragma unroll
    for (int mi = 0; mi < 2; mi++) {
        int r = wm * 32 + mi * 16 + rowA;
        int sw = (r >> 1) & 3;
        aAddr[mi] = (uint32_t)((r * 16 + ((gA ^ sw) * 4)) << 2);
    }
    #pragma unroll
    for (int pr = 0; pr < PR; pr++) {
        int r = wn * (BN / 2) + pr * 16 + rowB;
        int sw = (r >> 1) & 3;
        bAddr[pr] = (uint32_t)((B_OFF + r * 16 + ((gB ^ sw) * 4)) << 2);
    }

    float acc[2][NI][4] = {};
    const int nck = Kp >> 5;

    auto load_tile = [&](int ck, int st) {
        const uint32_t stg = sbase + (uint32_t)(st * STG_B);
        const int k0 = ck * 16;
        #pragma unroll
        for (int i = 0; i < TA / 256; i++) {
            int idx = tid + i * 256;
            int arr = idx >> 9, rem = idx & 511;
            int r = rem >> 2, c4 = rem & 3;
            int sw = c4 ^ ((r >> 1) & 3);
            int gm = m0 + r;
            bool ok = gm < M;
            const uint32_t* base = arr ? Al : Ah;
            const uint32_t* src = ok ? (base + (size_t)gm * Kp2 + k0 + c4 * 4) : base;
            cp16(stg + ((arr * 2048 + r * 16 + sw * 4) << 2), src, ok);
        }
        #pragma unroll
        for (int i = 0; i < (TB + 255) / 256; i++) {
            int idx = tid + i * 256;
            if (TB % 256 == 0 || idx < TB) {
                int arr = idx / (4 * BN);
                int rem = idx - arr * 4 * BN;
                int r = rem >> 2, c4 = rem & 3;
                int sw = c4 ^ ((r >> 1) & 3);
                int gn = n0 + r;
                bool ok = gn < N;
                const uint32_t* base = arr ? Bl : Bh;
                const uint32_t* src = ok ? (base + (size_t)gn * Kp2 + k0 + c4 * 4) : base;
                cp16(stg + ((B_OFF + arr * (BN * 16) + r * 16 + sw * 4) << 2), src, ok);
            }
        }
    };

    #pragma unroll
    for (int p = 0; p < NSTAGE - 1; p++) {
        if (p < nck) load_tile(p, p);
        CP_COMMIT();
    }

    for (int ck = 0; ck < nck; ck++) {
        asm volatile("cp.async.wait_group %0;" :: "n"(NSTAGE - 2) : "memory");
        __syncthreads();

        if (ck + NSTAGE - 1 < nck) load_tile(ck + NSTAGE - 1, (ck + NSTAGE - 1) & 3);
        CP_COMMIT();

        const uint32_t stg = sbase + (uint32_t)((ck & 3) * STG_B);

        #pragma unroll
        for (int kk = 0; kk < 2; kk++) {
            const uint32_t kx = kk ? 32u : 0u;
            uint32_t a_h[2][4], a_l[2][4], b_h[NI][2], b_l[NI][2];
            #pragma unroll
            for (int mi = 0; mi < 2; mi++) {
                uint32_t ad = (stg + aAddr[mi]) ^ kx;
                ldsm4(a_h[mi], ad);
                ldsm4(a_l[mi], ad + 8192);
            }
            #pragma unroll
            for (int pr = 0; pr < PR; pr++) {
                uint32_t bd = (stg + bAddr[pr]) ^ kx;
                uint32_t bt[4];
                ldsm4(bt, bd);
                b_h[2 * pr][0] = bt[0]; b_h[2 * pr][1] = bt[1];
                b_h[2 * pr + 1][0] = bt[2]; b_h[2 * pr + 1][1] = bt[3];
                ldsm4(bt, bd + (uint32_t)(BN * 16 * 4));
                b_l[2 * pr][0] = bt[0]; b_l[2 * pr][1] = bt[1];
                b_l[2 * pr + 1][0] = bt[2]; b_l[2 * pr + 1][1] = bt[3];
            }
            #pragma unroll
            for (int mi = 0; mi < 2; mi++)
                #pragma unroll
                for (int ni = 0; ni < NI; ni++) {
                    mma_bf16(acc[mi][ni], a_h[mi], b_h[ni]);
                    mma_bf16(acc[mi][ni], a_h[mi], b_l[ni]);
                    mma_bf16(acc[mi][ni], a_l[mi], b_h[ni]);
                }
        }
    }

    const int N2 = N >> 1;
    #pragma unroll
    for (int mi = 0; mi < 2; mi++) {
        int r0 = m0 + wm * 32 + mi * 16 + l4;
        #pragma unroll
        for (int ni = 0; ni < NI; ni++) {
            int c0 = n0 + wn * (BN / 2) + ni * 8 + 2 * lk;
            if (c0 < N) {
                float v0 = alpha * acc[mi][ni][0], v1 = alpha * acc[mi][ni][1];
                float v2 = alpha * acc[mi][ni][2], v3 = alpha * acc[mi][ni][3];
                int pj = c0 >> 1;
                if (r0 < M) {
                    uint32_t hi, lo;
                    split_pair(v0, v1, hi, lo);
                    Ch[sC * b + (size_t)r0 * N2 + pj] = hi;
                    Cl[sC * b + (size_t)r0 * N2 + pj] = lo;
                }
                if (r0 + 8 < M) {
                    uint32_t hi, lo;
                    split_pair(v2, v3, hi, lo);
                    Ch[sC * b + (size_t)(r0 + 8) * N2 + pj] = hi;
                    Cl[sC * b + (size_t)(r0 + 8) * N2 + pj] = lo;
                }
            }
        }
    }
}

// ---------------------------------------------------------------------------
// Fused steps 3+4+5: logits GEMM (A = Y block resident in smem, B = Hh
// streamed through a 4-deep ring) + per-row smem max + per-row candidate
// scan (global lists, capacity CAPG >= T: no overflow) + exact recompute +
// softmax + gather. grid (3,1,64), 256 thr, 2 CTAs/SM. Deterministic.
// ---------------------------------------------------------------------------
__global__ __launch_bounds__(256, 2)
void attn_fused(const uint32_t* __restrict__ Yh, const uint32_t* __restrict__ Yl,
                const uint32_t* __restrict__ Hh, const float* __restrict__ Hf,
                uint32_t* __restrict__ Lb,
                uint32_t* __restrict__ CI, float* __restrict__ CL,
                float* __restrict__ out)
{
    constexpr int NT = 15, NCK = 6, NSTEP = NT * NCK;   // 90 steps
    constexpr int B_OFF = 12288;    // after 6 A slabs x 2048 u32
    constexpr int RM_OFF = 18432;   // rowmax[128]

    extern __shared__ uint32_t sm[];
    const uint32_t sbase = (uint32_t)__cvta_generic_to_shared(sm);

    const int b = blockIdx.z;
    const int m0 = blockIdx.x * 128;
    const int tid = threadIdx.x;
    const int warp = tid >> 5, lane = tid & 31;
    const int wm = warp >> 1, wn = warp & 1;
    const int l4 = lane >> 2, lk = lane & 3;
    const float scale = 1.0f / sqrtf((float)XD * (float)HD);

    // batch offsets
    Yh += (size_t)b * CN * HP2;
    Yl += (size_t)b * CN * HP2;
    Hh += (size_t)b * T_ * HP2;

    const int lt = lane >> 3, lr8 = lane & 7;
    const int rowA = (lt & 1) * 8 + lr8;
    const int gA = lt >> 1;
    const int rowB = (lt >> 1) * 8 + lr8;
    const int gB = lt & 1;
    uint32_t aAddr[2], bAddr[3];
    #pragma unroll
    for (int mi = 0; mi < 2; mi++) {
        int r = wm * 32 + mi * 16 + rowA;
        int sw = (r >> 1) & 3;
        aAddr[mi] = (uint32_t)((r * 16 + ((gA ^ sw) * 4)) << 2);
    }
    #pragma unroll
    for (int pr = 0; pr < 3; pr++) {
        int r = wn * 48 + pr * 16 + rowB;
        int sw = (r >> 1) & 3;
        bAddr[pr] = (uint32_t)((r * 16 + ((gB ^ sw) * 4)) << 2);
    }

    if (tid < 128) sm[RM_OFF + tid] = 0u;

    // ---- load A (Yh block, 128 x 96 u32) into 6 swizzled slabs, once ----
    #pragma unroll
    for (int i = 0; i < 12; i++) {
        int idx = tid + i * 256;                 // 3072 chunks
        int r = idx / 24;
        int g = idx - r * 24;
        int slab = g >> 2, c4 = g & 3;
        int gm = m0 + r;
        bool ok = gm < CN;
        int sw = c4 ^ ((r >> 1) & 3);
        const uint32_t* src = ok ? (Yh + (size_t)gm * HP2 + slab * 16 + c4 * 4) : Yh;
        cp16(sbase + ((slab * 2048 + r * 16 + sw * 4) << 2), src, ok);
    }
    CP_COMMIT();

    auto loadB = [&](int s) {
        int tile = s / NCK, ck = s - tile * NCK;
        int st = s & 3;
        #pragma unroll
        for (int i = 0; i < 2; i++) {
            int idx = tid + i * 256;
            if (idx < 384) {                     // 96 rows x 4 groups
                int r = idx >> 2, c4 = idx & 3;
                int gn = tile * 96 + r;
                bool ok = gn < T_;
                int sw = c4 ^ ((r >> 1) & 3);
                const uint32_t* src = ok ? (Hh + (size_t)gn * HP2 + ck * 16 + c4 * 4) : Hh;
                cp16(sbase + ((B_OFF + st * 1536 + r * 16 + sw * 4) << 2), src, ok);
            }
        }
    };

    loadB(0); CP_COMMIT();
    loadB(1); CP_COMMIT();
    loadB(2); CP_COMMIT();

    float acc[2][6][4] = {};

    for (int s = 0; s < NSTEP; s++) {
        asm volatile("cp.async.wait_group 2;" ::: "memory");
        __syncthreads();
        if (s + 3 < NSTEP) loadB(s + 3);
        CP_COMMIT();

        const uint32_t abase = sbase + (uint32_t)((s % NCK) * 8192);
        const uint32_t bbase = sbase + (uint32_t)((B_OFF + (s & 3) * 1536) << 2);

        #pragma unroll
        for (int kk = 0; kk < 2; kk++) {
            const uint32_t kx = kk ? 32u : 0u;
            uint32_t a_h[2][4], b_h[6][2];
            #pragma unroll
            for (int mi = 0; mi < 2; mi++)
                ldsm4(a_h[mi], (abase + aAddr[mi]) ^ kx);
            #pragma unroll
            for (int pr = 0; pr < 3; pr++) {
                uint32_t bt[4];
                ldsm4(bt, (bbase + bAddr[pr]) ^ kx);
                b_h[2 * pr][0] = bt[0]; b_h[2 * pr][1] = bt[1];
                b_h[2 * pr + 1][0] = bt[2]; b_h[2 * pr + 1][1] = bt[3];
            }
            #pragma unroll
            for (int mi = 0; mi < 2; mi++)
                #pragma unroll
                for (int ni = 0; ni < 6; ni++)
                    mma_bf16(acc[mi][ni], a_h[mi], b_h[ni]);
        }

        if (s % NCK == NCK - 1) {
            const int tile = s / NCK;
            #pragma unroll
            for (int mi = 0; mi < 2; mi++) {
                int lr0 = wm * 32 + mi * 16 + l4;
                int r0 = m0 + lr0;
                float mx0 = -CUDART_INF_F, mx1 = -CUDART_INF_F;
                #pragma unroll
                for (int ni = 0; ni < 6; ni++) {
                    int c0 = tile * 96 + wn * 48 + ni * 8 + 2 * lk;
                    if (c0 < T_) {
                        __nv_bfloat16 q0 = __float2bfloat16_rn(scale * acc[mi][ni][0]);
                        __nv_bfloat16 q1 = __float2bfloat16_rn(scale * acc[mi][ni][1]);
                        __nv_bfloat16 q2 = __float2bfloat16_rn(scale * acc[mi][ni][2]);
                        __nv_bfloat16 q3 = __float2bfloat16_rn(scale * acc[mi][ni][3]);
                        if (r0 < CN) {
                            Lb[((size_t)b * CN + r0) * T2 + (c0 >> 1)] =
                                ((uint32_t)__bfloat16_as_ushort(q1) << 16) | __bfloat16_as_ushort(q0);
                            mx0 = fmaxf(mx0, fmaxf(__bfloat162float(q0), __bfloat162float(q1)));
                        }
                        if (r0 + 8 < CN) {
                            Lb[((size_t)b * CN + r0 + 8) * T2 + (c0 >> 1)] =
                                ((uint32_t)__bfloat16_as_ushort(q3) << 16) | __bfloat16_as_ushort(q2);
                            mx1 = fmaxf(mx1, fmaxf(__bfloat162float(q2), __bfloat162float(q3)));
                        }
                    }
                    acc[mi][ni][0] = 0.f; acc[mi][ni][1] = 0.f;
                    acc[mi][ni][2] = 0.f; acc[mi][ni][3] = 0.f;
                }
                #pragma unroll
                for (int o = 1; o <= 2; o <<= 1) {
                    mx0 = fmaxf(mx0, __shfl_xor_sync(0xffffffffu, mx0, o));
                    mx1 = fmaxf(mx1, __shfl_xor_sync(0xffffffffu, mx1, o));
                }
                if (lk == 0) {
                    if (mx0 > -CUDART_INF_F) atomicMax(&sm[RM_OFF + lr0], enc_f(mx0));
                    if (mx1 > -CUDART_INF_F) atomicMax(&sm[RM_OFF + lr0 + 8], enc_f(mx1));
                }
            }
        }
    }

    asm volatile("cp.async.wait_group 0;" ::: "memory");
    __threadfence_block();
    __syncthreads();

    // ---- per-row: scan + exact recompute + softmax + gather (warp per row) ----
    const int lrb = warp * 16;
    for (int q = 0; q < 16; q++) {
        int lrow = lrb + q;
        int gm = m0 + lrow;
        if (gm >= CN) continue;
        const size_t rowg = (size_t)b * CN + gm;
        float thr = dec_f(sm[RM_OFF + lrow]) - (THR_LN + SLACK);
        const uint32_t* LbRow = Lb + rowg * T2;
        uint32_t* CIrow = CI + rowg * CAPG;
        float*    CLrow = CL + rowg * CAPG;

        // 1) ballot-ordered candidate scan (deterministic; no capacity limit)
        int base = 0;
        for (int i0 = 0; i0 < 1408; i0 += 32) {
            int i = i0 + lane;
            float l = -CUDART_INF_F;
            if (i < T_) {
                uint32_t u = LbRow[i >> 1];
                l = (i & 1) ? bf_hi(u) : bf_lo(u);
            }
            bool k = l > thr;
            unsigned bal = __ballot_sync(0xffffffffu, k);
            int o = __popc(bal & ((1u << lane) - 1u));
            if (k) CIrow[base + o] = (uint32_t)i;
            base += __popc(bal);
        }
        const int n = base;
        __threadfence_block();
        __syncwarp();

        // 2) exact logits for candidates (warp per candidate, fixed order)
        for (int j = 0; j < n; j++) {
            uint32_t u = CIrow[j];
            const float* Hu = Hf + ((size_t)b * T_ + u) * HD;
            float s = 0.f;
            for (int d = lane; d < HD; d += 32) {
                uint32_t uh = Yh[(size_t)gm * HP2 + (d >> 1)];
                uint32_t ul = Yl[(size_t)gm * HP2 + (d >> 1)];
                float y = ((d & 1) ? bf_hi(uh) : bf_lo(uh))
                        + ((d & 1) ? bf_hi(ul) : bf_lo(ul));
                s += y * Hu[d];
            }
            #pragma unroll
            for (int o = 16; o > 0; o >>= 1)
                s += __shfl_xor_sync(0xffffffffu, s, o);
            if (lane == 0) CLrow[j] = s * scale;
        }
        __threadfence_block();
        __syncwarp();

        // 3) softmax over candidates (lane-strided, fixed-order reductions)
        float m = -CUDART_INF_F;
        for (int j = lane; j < n; j += 32) m = fmaxf(m, CLrow[j]);
        #pragma unroll
        for (int o = 16; o > 0; o >>= 1)
            m = fmaxf(m, __shfl_xor_sync(0xffffffffu, m, o));
        float ssum = 0.f;
        for (int j = lane; j < n; j += 32) ssum += __expf(CLrow[j] - m);
        #pragma unroll
        for (int o = 16; o > 0; o >>= 1)
            ssum += __shfl_xor_sync(0xffffffffu, ssum, o);
        float inv = __frcp_rn(ssum);
        for (int j = lane; j < n; j += 32)
            CLrow[j] = __expf(CLrow[j] - m) * inv;
        __threadfence_block();
        __syncwarp();

        // 4) gather output row (fixed candidate order)
        float* Orow = out + rowg * HD;
        for (int d = lane; d < HD; d += 32) {
            float a = 0.f;
            for (int j = 0; j < n; j++)
                a += CLrow[j] * Hf[((size_t)b * T_ + CIrow[j]) * HD + d];
            Orow[d] = a;
        }
    }
}

// ---------------------------------------------------------------------------

static inline int cdiv(int a, int b) { return (a + b - 1) / b; }

extern "C" void kernel_launch(void* const* d_in, const int* in_sizes, int n_in,
                              void* d_out, int out_size) {
    const float* X  = (const float*)d_in[0];  // [B,T,XD]
    const float* H  = (const float*)d_in[1];  // [B,T,HD]
    const float* W1 = (const float*)d_in[2];  // [XD,HD]
    const float* W2 = (const float*)d_in[3];  // [CN,T]
    float* out = (float*)d_out;               // [B,CN,HD]

    uint32_t *W2h, *W2l, *Xth, *Xtl, *W1th, *W1tl, *Hh;
    uint32_t *Zh, *Zl, *Yh, *Yl, *Lb, *CI;
    float *CL;
    cudaGetSymbolAddress((void**)&W2h, g_W2h);  cudaGetSymbolAddress((void**)&W2l, g_W2l);
    cudaGetSymbolAddress((void**)&Xth, g_Xth);  cudaGetSymbolAddress((void**)&Xtl, g_Xtl);
    cudaGetSymbolAddress((void**)&W1th, g_W1th); cudaGetSymbolAddress((void**)&W1tl, g_W1tl);
    cudaGetSymbolAddress((void**)&Hh, g_Hh);
    cudaGetSymbolAddress((void**)&Zh, g_Zh);    cudaGetSymbolAddress((void**)&Zl, g_Zl);
    cudaGetSymbolAddress((void**)&Yh, g_Yh);    cudaGetSymbolAddress((void**)&Yl, g_Yl);
    cudaGetSymbolAddress((void**)&Lb, g_Lb);
    cudaGetSymbolAddress((void**)&CI, g_CI);
    cudaGetSymbolAddress((void**)&CL, g_CL);

    constexpr int SMEM3 = 4 * (4096 + 96 * 32) * 4;   // 114688 B (split GEMM)
    constexpr int SMEMF = (18432 + 128) * 4;          // 74240 B  (fused kernel)

    static bool attr_done = false;
    if (!attr_done) {
        cudaFuncSetAttribute(gemm_bf16s<96>,
            cudaFuncAttributeMaxDynamicSharedMemorySize, SMEM3);
        cudaFuncSetAttribute(attn_fused,
            cudaFuncAttributeMaxDynamicSharedMemorySize, SMEMF);
        attr_done = true;
    }

    // ---- prepass ----
    {
        size_t tot = (size_t)CN * TP2;
        split_pack<<<(int)cdiv((int)tot, 256), 256>>>(W2, W2h, W2l, CN, T_, TP2);
    }
    {
        size_t tot = (size_t)B_ * T_ * HP2;
        pack_hi<<<(int)((tot + 255) / 256), 256>>>(H, Hh, B_ * T_, HD, HP2);
    }
    split_transpose<<<dim3(TP / 32, cdiv(XD, 32), B_), dim3(32, 8)>>>(
        X, (size_t)T_ * XD, Xth, Xtl, (size_t)XD * TP2, T_, XD, TP2);
    split_transpose<<<dim3(XD / 32, cdiv(HD, 32), 1), dim3(32, 8)>>>(
        W1, 0, W1th, W1tl, 0, XD, HD, XP2);

    // 1) Z[b] = W2 @ X[b]    (3-product split, split output)
    gemm_bf16s<96><<<dim3(cdiv(CN, 128), cdiv(XD, 96), B_), 256, SMEM3>>>(
        W2h, W2l, 0, Xth, Xtl, (size_t)XD * TP2,
        Zh, Zl, (size_t)CN * XP2, CN, XD, TP, 1.0f);

    // 2) Y[b] = Z[b] @ W1    (3-product split, split output)
    gemm_bf16s<96><<<dim3(cdiv(CN, 128), cdiv(HD, 96), B_), 256, SMEM3>>>(
        Zh, Zl, (size_t)CN * XP2, W1th, W1tl, 0,
        Yh, Yl, (size_t)CN * HP2, CN, HD, XD, 1.0f);

    // 3+4+5) fused logits GEMM + max + candidate scan + exact softmax + gather
    attn_fused<<<dim3(cdiv(CN, 128), 1, B_), 256, SMEMF>>>(
        Yh, Yl, Hh, H, Lb, CI, CL, out);
}

// round 17
// speedup vs baseline: 2.3845x; 2.3845x over previous
#include <cuda_runtime.h>
#include <cuda_bf16.h>
#include <math_constants.h>
#include <cstdint>

#define B_  64
#define T_  1380
#define T2  (T_/2)      // 690 bf16 pairs per L row
#define TP  1408        // T padded to multiple of 32
#define TP2 (TP/2)      // 704 packed pairs
#define XD  96
#define XP2 (XD/2)      // 48
#define HD  192
#define HP2 (HD/2)      // 96
#define CN  345

#define THR_LN   18.421f   // -ln(1e-8)
#define SLACK    2.0f      // covers bf16-product + bf16-storage logit error (bound ~1.2)

// ---------------------------------------------------------------------------
// Scratch (device globals). hi/lo bf16 pairs packed in uint32 (low = lower k).
// ---------------------------------------------------------------------------
__device__ uint32_t g_W2h[(size_t)CN * TP2],      g_W2l[(size_t)CN * TP2];
__device__ uint32_t g_Xth[(size_t)B_ * XD * TP2], g_Xtl[(size_t)B_ * XD * TP2];
__device__ uint32_t g_W1th[(size_t)HD * XP2],     g_W1tl[(size_t)HD * XP2];
__device__ uint32_t g_Hh [(size_t)B_ * T_ * HP2];
__device__ float    g_Zp [(size_t)2 * B_ * CN * XD];   // k-split fp32 partials
__device__ uint32_t g_Zh [(size_t)B_ * CN * XP2], g_Zl [(size_t)B_ * CN * XP2];
__device__ uint32_t g_Yh [(size_t)B_ * CN * HP2], g_Yl [(size_t)B_ * CN * HP2];
__device__ uint32_t g_Lb [(size_t)B_ * CN * T2];  // bf16x2 packed logits
__device__ uint32_t g_Mx [(size_t)B_ * CN];       // ordered-uint row max (of stored bf16)

// ---------------------------------------------------------------------------
// Helpers
// ---------------------------------------------------------------------------
__device__ __forceinline__ uint32_t enc_f(float f) {
    uint32_t u = __float_as_uint(f);
    return (u & 0x80000000u) ? ~u : (u | 0x80000000u);
}
__device__ __forceinline__ float dec_f(uint32_t k) {
    uint32_t u = (k & 0x80000000u) ? (k ^ 0x80000000u) : ~k;
    return __uint_as_float(u);
}

__device__ __forceinline__ void split_pair(float x0, float x1,
                                           uint32_t& hi, uint32_t& lo) {
    __nv_bfloat16 h0 = __float2bfloat16_rn(x0);
    __nv_bfloat16 h1 = __float2bfloat16_rn(x1);
    float r0 = x0 - __bfloat162float(h0);
    float r1 = x1 - __bfloat162float(h1);
    __nv_bfloat16 l0 = __float2bfloat16_rn(r0);
    __nv_bfloat16 l1 = __float2bfloat16_rn(r1);
    hi = ((uint32_t)__bfloat16_as_ushort(h1) << 16) | __bfloat16_as_ushort(h0);
    lo = ((uint32_t)__bfloat16_as_ushort(l1) << 16) | __bfloat16_as_ushort(l0);
}

__device__ __forceinline__ float bf_lo(uint32_t u) {
    return __bfloat162float(__ushort_as_bfloat16((unsigned short)(u & 0xffffu)));
}
__device__ __forceinline__ float bf_hi(uint32_t u) {
    return __bfloat162float(__ushort_as_bfloat16((unsigned short)(u >> 16)));
}

__device__ __forceinline__ void mma_bf16(float* c, const uint32_t* a, const uint32_t* b) {
    asm volatile(
        "mma.sync.aligned.m16n8k16.row.col.f32.bf16.bf16.f32 "
        "{%0,%1,%2,%3}, {%4,%5,%6,%7}, {%8,%9}, {%0,%1,%2,%3};"
        : "+f"(c[0]), "+f"(c[1]), "+f"(c[2]), "+f"(c[3])
        : "r"(a[0]), "r"(a[1]), "r"(a[2]), "r"(a[3]),
          "r"(b[0]), "r"(b[1]));
}

__device__ __forceinline__ void ldsm4(uint32_t* r, uint32_t saddr) {
    asm volatile("ldmatrix.sync.aligned.m8n8.x4.shared.b16 {%0,%1,%2,%3}, [%4];"
                 : "=r"(r[0]), "=r"(r[1]), "=r"(r[2]), "=r"(r[3]) : "r"(saddr));
}

__device__ __forceinline__ void cp16(uint32_t dst, const void* src, bool ok) {
    asm volatile(
        "{\n\t.reg .pred p;\n\t.reg .b32 sz;\n\t"
        "setp.ne.u32 p, %2, 0;\n\t"
        "selp.b32 sz, 16, 0, p;\n\t"
        "cp.async.cg.shared.global [%0], [%1], 16, sz;\n\t}"
        :: "r"(dst), "l"(src), "r"((uint32_t)ok) : "memory");
}
#define CP_COMMIT() asm volatile("cp.async.commit_group;" ::: "memory")

// ---------------------------------------------------------------------------
// Prepass kernels
// ---------------------------------------------------------------------------
__global__ void split_pack(const float* __restrict__ src,
                           uint32_t* __restrict__ dh, uint32_t* __restrict__ dl,
                           int rows, int C, int Cp2) {
    size_t idx = (size_t)blockIdx.x * 256 + threadIdx.x;
    size_t total = (size_t)rows * Cp2;
    if (idx >= total) return;
    int r = (int)(idx / Cp2);
    int j = (int)(idx - (size_t)r * Cp2);
    float2 v = make_float2(0.f, 0.f);
    if (2 * j < C)
        v = *reinterpret_cast<const float2*>(src + (size_t)r * C + 2 * j);
    uint32_t hi, lo;
    split_pair(v.x, v.y, hi, lo);
    dh[idx] = hi;
    dl[idx] = lo;
}

__global__ void pack_hi(const float* __restrict__ src,
                        uint32_t* __restrict__ dh, int rows, int C, int Cp2) {
    size_t idx = (size_t)blockIdx.x * 256 + threadIdx.x;
    size_t total = (size_t)rows * Cp2;
    if (idx >= total) return;
    int r = (int)(idx / Cp2);
    int j = (int)(idx - (size_t)r * Cp2);
    float2 v = make_float2(0.f, 0.f);
    if (2 * j < C)
        v = *reinterpret_cast<const float2*>(src + (size_t)r * C + 2 * j);
    __nv_bfloat16 h0 = __float2bfloat16_rn(v.x);
    __nv_bfloat16 h1 = __float2bfloat16_rn(v.y);
    dh[idx] = ((uint32_t)__bfloat16_as_ushort(h1) << 16) | __bfloat16_as_ushort(h0);
}

__global__ void split_transpose(const float* __restrict__ src, size_t sSrc,
                                uint32_t* __restrict__ dh, uint32_t* __restrict__ dl,
                                size_t sDst, int R, int C, int Rp2) {
    __shared__ float t[32][33];
    const int b = blockIdx.z;
    src += sSrc * b;
    dh  += sDst * b;
    dl  += sDst * b;
    const int r0 = blockIdx.x * 32;
    const int c0 = blockIdx.y * 32;
    const int tx = threadIdx.x, ty = threadIdx.y;

    #pragma unroll
    for (int i = 0; i < 4; i++) {
        int r = r0 + ty + i * 8, c = c0 + tx;
        t[ty + i * 8][tx] = (r < R && c < C) ? src[(size_t)r * C + c] : 0.f;
    }
    __syncthreads();
    if (tx < 16) {
        #pragma unroll
        for (int i = 0; i < 4; i++) {
            int cc = ty + i * 8, c = c0 + cc;
            if (c < C) {
                uint32_t hi, lo;
                split_pair(t[2 * tx][cc], t[2 * tx + 1][cc], hi, lo);
                size_t o = (size_t)c * Rp2 + (r0 >> 1) + tx;
                dh[o] = hi;
                dl[o] = lo;
            }
        }
    }
}

__global__ void init_max() {
    int i = blockIdx.x * 256 + threadIdx.x;
    if (i < B_ * CN) g_Mx[i] = 0u;
}

// Combine k-split fp32 partials and emit split-bf16 Z.
__global__ void combine_split() {
    size_t idx = (size_t)blockIdx.x * 256 + threadIdx.x;
    constexpr size_t TOT = (size_t)B_ * CN * XP2;
    if (idx >= TOT) return;
    float2 a = reinterpret_cast<const float2*>(g_Zp)[idx];
    float2 c = reinterpret_cast<const float2*>(g_Zp + (size_t)B_ * CN * XD)[idx];
    uint32_t hi, lo;
    split_pair(a.x + c.x, a.y + c.y, hi, lo);
    g_Zh[idx] = hi;
    g_Zl[idx] = lo;
}

// ---------------------------------------------------------------------------
// bf16 tensor-core GEMM (NT, packed bf16-pair operands).
//   C[b] = alpha * A[b] (M x Kp) @ B[b] (N x Kp)^T
// PROD==3: split-compensated (hh+hl+lh), PROD==1: hi*hi only.
// MODE==0: fp32 out with K-SPLIT x2 (blockIdx.y = k-half, disjoint buffers).
// MODE==1: write split Ch/Cl; MODE==2: write packed-bf16 Ch + atomicMax Mx.
// BM=128, BN templated, BK=32, 256 threads (8 warps 4x2), warp tile 32 x BN/2.
// 4-stage cp.async pipeline, XOR-swizzled pitch-16 smem.
// ---------------------------------------------------------------------------
template<int BN, int MODE, int PROD>
__global__ __launch_bounds__(256, 2)
void gemm_bf16s(const uint32_t* __restrict__ Ah, const uint32_t* __restrict__ Al, size_t sA,
                const uint32_t* __restrict__ Bh, const uint32_t* __restrict__ Bl, size_t sB,
                uint32_t* __restrict__ Ch, uint32_t* __restrict__ Cl,
                uint32_t* __restrict__ Mx,
                size_t sC, int M, int N, int Kp, float alpha)
{
    constexpr int NI = BN / 16;
    constexpr int PR = BN / 32;
    constexpr int NARR = (PROD == 3) ? 2 : 1;
    constexpr int A_U32 = 2048 * NARR;
    constexpr int B_OFF = A_U32;                 // u32 offset of B-hi
    constexpr int B_U32 = BN * 16 * NARR;
    constexpr int STG_U32 = A_U32 + B_U32;
    constexpr int STG_B = STG_U32 * 4;
    constexpr int NSTAGE = 4;
    constexpr int TA = NARR * 512;               // A 16B-chunks per stage
    constexpr int TB = NARR * BN * 4;            // B 16B-chunks per stage

    extern __shared__ uint32_t sm[];
    const uint32_t sbase = (uint32_t)__cvta_generic_to_shared(sm);

    const int b = blockIdx.z;
    Ah += sA * b;  Al += sA * b;
    Bh += sB * b;  Bl += sB * b;
    const int m0 = blockIdx.x * 128;
    const int n0 = (MODE == 0) ? 0 : blockIdx.y * BN;
    const int tid  = threadIdx.x;
    const int warp = tid >> 5, lane = tid & 31;
    const int wm = warp >> 1, wn = warp & 1;
    const int l4 = lane >> 2, lk = lane & 3;
    const int Kp2 = Kp >> 1;
    const int kb2 = (MODE == 0) ? (int)blockIdx.y * (Kp2 >> 1) : 0; // k-half base (u32)

    const int lt = lane >> 3, lr = lane & 7;
    const int rowA = (lt & 1) * 8 + lr;
    const int gA   = lt >> 1;
    const int rowB = (lt >> 1) * 8 + lr;
    const int gB   = lt & 1;

    uint32_t aAddr[2], bAddr[PR];
    #pragma unroll
    for (int mi = 0; mi < 2; mi++) {
        int r = wm * 32 + mi * 16 + rowA;
        int sw = (r >> 1) & 3;
        aAddr[mi] = (uint32_t)((r * 16 + ((gA ^ sw) * 4)) << 2);
    }
    #pragma unroll
    for (int pr = 0; pr < PR; pr++) {
        int r = wn * (BN / 2) + pr * 16 + rowB;
        int sw = (r >> 1) & 3;
        bAddr[pr] = (uint32_t)((B_OFF + r * 16 + ((gB ^ sw) * 4)) << 2);
    }

    float acc[2][NI][4] = {};
    const int nck = (MODE == 0) ? (Kp >> 6) : (Kp >> 5);

    auto load_tile = [&](int ck, int st) {
        const uint32_t stg = sbase + (uint32_t)(st * STG_B);
        const int k0 = kb2 + ck * 16;
        #pragma unroll
        for (int i = 0; i < (TA + 255) / 256; i++) {
            int idx = tid + i * 256;
            if (TA % 256 == 0 || idx < TA) {
                int arr = idx >> 9, rem = idx & 511;
                int r = rem >> 2, c4 = rem & 3;
                int sw = c4 ^ ((r >> 1) & 3);
                int gm = m0 + r;
                bool ok = gm < M;
                const uint32_t* base = arr ? Al : Ah;
                const uint32_t* src = ok ? (base + (size_t)gm * Kp2 + k0 + c4 * 4) : base;
                cp16(stg + ((arr * 2048 + r * 16 + sw * 4) << 2), src, ok);
            }
        }
        #pragma unroll
        for (int i = 0; i < (TB + 255) / 256; i++) {
            int idx = tid + i * 256;
            if (TB % 256 == 0 || idx < TB) {
                int arr = idx / (4 * BN);
                int rem = idx - arr * 4 * BN;
                int r = rem >> 2, c4 = rem & 3;
                int sw = c4 ^ ((r >> 1) & 3);
                int gn = n0 + r;
                bool ok = gn < N;
                const uint32_t* base = arr ? Bl : Bh;
                const uint32_t* src = ok ? (base + (size_t)gn * Kp2 + k0 + c4 * 4) : base;
                cp16(stg + ((B_OFF + arr * (BN * 16) + r * 16 + sw * 4) << 2), src, ok);
            }
        }
    };

    #pragma unroll
    for (int p = 0; p < NSTAGE - 1; p++) {
        if (p < nck) load_tile(p, p);
        CP_COMMIT();
    }

    for (int ck = 0; ck < nck; ck++) {
        asm volatile("cp.async.wait_group %0;" :: "n"(NSTAGE - 2) : "memory");
        __syncthreads();

        if (ck + NSTAGE - 1 < nck) load_tile(ck + NSTAGE - 1, (ck + NSTAGE - 1) & 3);
        CP_COMMIT();

        const uint32_t stg = sbase + (uint32_t)((ck & 3) * STG_B);

        #pragma unroll
        for (int kk = 0; kk < 2; kk++) {
            const uint32_t kx = kk ? 32u : 0u;
            uint32_t a_h[2][4], a_l[2][4], b_h[NI][2], b_l[NI][2];
            #pragma unroll
            for (int mi = 0; mi < 2; mi++) {
                uint32_t ad = (stg + aAddr[mi]) ^ kx;
                ldsm4(a_h[mi], ad);
                if (PROD == 3) ldsm4(a_l[mi], ad + 8192);
            }
            #pragma unroll
            for (int pr = 0; pr < PR; pr++) {
                uint32_t bd = (stg + bAddr[pr]) ^ kx;
                uint32_t bt[4];
                ldsm4(bt, bd);
                b_h[2 * pr][0] = bt[0]; b_h[2 * pr][1] = bt[1];
                b_h[2 * pr + 1][0] = bt[2]; b_h[2 * pr + 1][1] = bt[3];
                if (PROD == 3) {
                    ldsm4(bt, bd + (uint32_t)(BN * 16 * 4));
                    b_l[2 * pr][0] = bt[0]; b_l[2 * pr][1] = bt[1];
                    b_l[2 * pr + 1][0] = bt[2]; b_l[2 * pr + 1][1] = bt[3];
                }
            }
            #pragma unroll
            for (int mi = 0; mi < 2; mi++)
                #pragma unroll
                for (int ni = 0; ni < NI; ni++) {
                    mma_bf16(acc[mi][ni], a_h[mi], b_h[ni]);
                    if (PROD == 3) {
                        mma_bf16(acc[mi][ni], a_h[mi], b_l[ni]);
                        mma_bf16(acc[mi][ni], a_l[mi], b_h[ni]);
                    }
                }
        }
    }

    // ---- epilogue ----
    const int N2 = N >> 1;
    #pragma unroll
    for (int mi = 0; mi < 2; mi++) {
        int r0 = m0 + wm * 32 + mi * 16 + l4;
        float mx0 = -CUDART_INF_F, mx1 = -CUDART_INF_F;
        #pragma unroll
        for (int ni = 0; ni < NI; ni++) {
            int c0 = n0 + wn * (BN / 2) + ni * 8 + 2 * lk;
            if (c0 < N) {
                float v0 = alpha * acc[mi][ni][0], v1 = alpha * acc[mi][ni][1];
                float v2 = alpha * acc[mi][ni][2], v3 = alpha * acc[mi][ni][3];
                int pj = c0 >> 1;
                if (MODE == 0) {
                    float* Cf = reinterpret_cast<float*>(Ch)
                              + (size_t)blockIdx.y * ((size_t)B_ * CN * XD);
                    if (r0 < M)
                        *reinterpret_cast<float2*>(Cf + sC * b + (size_t)r0 * N + c0)
                            = make_float2(v0, v1);
                    if (r0 + 8 < M)
                        *reinterpret_cast<float2*>(Cf + sC * b + (size_t)(r0 + 8) * N + c0)
                            = make_float2(v2, v3);
                } else if (MODE == 1) {
                    if (r0 < M) {
                        uint32_t hi, lo;
                        split_pair(v0, v1, hi, lo);
                        Ch[sC * b + (size_t)r0 * N2 + pj] = hi;
                        Cl[sC * b + (size_t)r0 * N2 + pj] = lo;
                    }
                    if (r0 + 8 < M) {
                        uint32_t hi, lo;
                        split_pair(v2, v3, hi, lo);
                        Ch[sC * b + (size_t)(r0 + 8) * N2 + pj] = hi;
                        Cl[sC * b + (size_t)(r0 + 8) * N2 + pj] = lo;
                    }
                } else {   // MODE == 2: packed bf16 logits + row max of stored values
                    __nv_bfloat16 q0 = __float2bfloat16_rn(v0);
                    __nv_bfloat16 q1 = __float2bfloat16_rn(v1);
                    __nv_bfloat16 q2 = __float2bfloat16_rn(v2);
                    __nv_bfloat16 q3 = __float2bfloat16_rn(v3);
                    if (r0 < M)
                        Ch[sC * b + (size_t)r0 * N2 + pj] =
                            ((uint32_t)__bfloat16_as_ushort(q1) << 16) | __bfloat16_as_ushort(q0);
                    if (r0 + 8 < M)
                        Ch[sC * b + (size_t)(r0 + 8) * N2 + pj] =
                            ((uint32_t)__bfloat16_as_ushort(q3) << 16) | __bfloat16_as_ushort(q2);
                    mx0 = fmaxf(mx0, fmaxf(__bfloat162float(q0), __bfloat162float(q1)));
                    mx1 = fmaxf(mx1, fmaxf(__bfloat162float(q2), __bfloat162float(q3)));
                }
            }
        }
        if (MODE == 2) {
            #pragma unroll
            for (int o = 1; o <= 2; o <<= 1) {
                mx0 = fmaxf(mx0, __shfl_xor_sync(0xffffffffu, mx0, o));
                mx1 = fmaxf(mx1, __shfl_xor_sync(0xffffffffu, mx1, o));
            }
            if (lk == 0 && mx0 > -CUDART_INF_F) {
                if (r0 < M)     atomicMax(&Mx[(size_t)b * M + r0], enc_f(mx0));
                if (r0 + 8 < M) atomicMax(&Mx[(size_t)b * M + r0 + 8], enc_f(mx1));
            }
        }
    }
}

// ---------------------------------------------------------------------------
// Sparse softmax-gather with exact recompute of candidate logits.
// Candidates: stored-bf16 logit > max_b - (THR_LN + SLACK). Exact logits
// recomputed as scale * (Yh+Yl) . H in fp32 (one warp per candidate).
// Deterministic: ballot-ordered compaction, fixed-order reductions.
// ---------------------------------------------------------------------------
#define SEG 173          // ceil(1380/8) elements per warp
#define CAP 176          // >= SEG: per-warp list cannot overflow

__global__ void softmax_gather(const float* __restrict__ H,
                               float* __restrict__ out) {
    const int c = blockIdx.x, b = blockIdx.y;
    const size_t row = (size_t)b * CN + c;
    const uint32_t* Lr = g_Lb + row * T2;
    const int tid = threadIdx.x;
    const int lane = tid & 31, warp = tid >> 5;
    const float scale = 1.0f / sqrtf((float)XD * (float)HD);

    const float M = dec_f(g_Mx[row]);
    const float thr = M - (THR_LN + SLACK);

    __shared__ uint32_t sidx[8 * CAP];
    __shared__ int      cnt[8];
    __shared__ int      off[9];
    __shared__ uint32_t fidx[T_];
    __shared__ float    flog[T_];
    __shared__ float    fp[T_];
    __shared__ float    sM2, sInv;

    // 1) one-pass candidate scan over stored bf16 logits
    {
        int s0 = warp * SEG;
        int s1 = min(s0 + SEG, T_);
        int base = 0;
        for (int i0 = s0; i0 < s1; i0 += 32) {
            int i = i0 + lane;
            float l = -CUDART_INF_F;
            if (i < s1) {
                uint32_t u = Lr[i >> 1];
                l = (i & 1) ? bf_hi(u) : bf_lo(u);
            }
            bool k = l > thr;
            unsigned bal = __ballot_sync(0xffffffffu, k);
            int o = __popc(bal & ((1u << lane) - 1u));
            if (k) sidx[warp * CAP + base + o] = (uint32_t)i;
            base += __popc(bal);
        }
        if (lane == 0) cnt[warp] = base;
    }
    __syncthreads();

    if (tid == 0) {
        int t = 0;
        #pragma unroll
        for (int w = 0; w < 8; w++) { off[w] = t; t += cnt[w]; }
        off[8] = t;
    }
    __syncthreads();
    {
        int n = cnt[warp], o = off[warp];
        for (int j = lane; j < n; j += 32)
            fidx[o + j] = sidx[warp * CAP + j];
    }
    __syncthreads();

    const int n = off[8];

    // 2) exact logits for candidates: one warp per candidate
    {
        const uint32_t* yh = g_Yh + row * HP2;
        const uint32_t* yl = g_Yl + row * HP2;
        for (int j = warp; j < n; j += 8) {
            const float* Hu = H + ((size_t)b * T_ + fidx[j]) * HD;
            float s = 0.f;
            for (int d = lane; d < HD; d += 32) {
                uint32_t uh = yh[d >> 1], ul = yl[d >> 1];
                float y = ((d & 1) ? bf_hi(uh) : bf_lo(uh))
                        + ((d & 1) ? bf_hi(ul) : bf_lo(ul));
                s += y * Hu[d];
            }
            #pragma unroll
            for (int o = 16; o > 0; o >>= 1)
                s += __shfl_xor_sync(0xffffffffu, s, o);
            if (lane == 0) flog[j] = s * scale;
        }
    }
    __syncthreads();

    // 3) exact softmax over candidates (thread 0, fixed order)
    if (tid == 0) {
        float M2 = -CUDART_INF_F;
        for (int j = 0; j < n; j++) M2 = fmaxf(M2, flog[j]);
        float S = 0.f;
        for (int j = 0; j < n; j++) S += __expf(flog[j] - M2);
        sM2 = M2;
        sInv = __frcp_rn(S);
    }
    __syncthreads();
    {
        float M2 = sM2, inv = sInv;
        for (int j = tid; j < n; j += 256)
            fp[j] = __expf(flog[j] - M2) * inv;
    }
    __syncthreads();

    // 4) gather output row (fixed order)
    const float* Hb = H + (size_t)b * T_ * HD;
    float* Orow = out + row * HD;
    for (int j = tid; j < HD; j += 256) {
        float a = 0.f;
        for (int k = 0; k < n; k++)
            a += fp[k] * Hb[(size_t)fidx[k] * HD + j];
        Orow[j] = a;
    }
}

// ---------------------------------------------------------------------------

static inline int cdiv(int a, int b) { return (a + b - 1) / b; }

extern "C" void kernel_launch(void* const* d_in, const int* in_sizes, int n_in,
                              void* d_out, int out_size) {
    const float* X  = (const float*)d_in[0];  // [B,T,XD]
    const float* H  = (const float*)d_in[1];  // [B,T,HD]
    const float* W1 = (const float*)d_in[2];  // [XD,HD]
    const float* W2 = (const float*)d_in[3];  // [CN,T]
    float* out = (float*)d_out;               // [B,CN,HD]

    uint32_t *W2h, *W2l, *Xth, *Xtl, *W1th, *W1tl, *Hh;
    uint32_t *Zh, *Zl, *Yh, *Yl, *Mx, *Lb;
    float *Zp;
    cudaGetSymbolAddress((void**)&W2h, g_W2h);  cudaGetSymbolAddress((void**)&W2l, g_W2l);
    cudaGetSymbolAddress((void**)&Xth, g_Xth);  cudaGetSymbolAddress((void**)&Xtl, g_Xtl);
    cudaGetSymbolAddress((void**)&W1th, g_W1th); cudaGetSymbolAddress((void**)&W1tl, g_W1tl);
    cudaGetSymbolAddress((void**)&Hh, g_Hh);
    cudaGetSymbolAddress((void**)&Zp, g_Zp);
    cudaGetSymbolAddress((void**)&Zh, g_Zh);    cudaGetSymbolAddress((void**)&Zl, g_Zl);
    cudaGetSymbolAddress((void**)&Yh, g_Yh);    cudaGetSymbolAddress((void**)&Yl, g_Yl);
    cudaGetSymbolAddress((void**)&Mx, g_Mx);
    cudaGetSymbolAddress((void**)&Lb, g_Lb);

    const float scale = 1.0f / sqrtf((float)XD * (float)HD);

    constexpr int SMEM3 = 4 * (4096 + 96 * 32) * 4;   // 114688 B (split GEMM)
    constexpr int SMEM1 = 4 * (2048 + 96 * 16) * 4;   // 57344 B  (single-product GEMM)

    static bool attr_done = false;
    if (!attr_done) {
        cudaFuncSetAttribute(gemm_bf16s<96, 0, 3>,
            cudaFuncAttributeMaxDynamicSharedMemorySize, SMEM3);
        cudaFuncSetAttribute(gemm_bf16s<96, 1, 3>,
            cudaFuncAttributeMaxDynamicSharedMemorySize, SMEM3);
        cudaFuncSetAttribute(gemm_bf16s<96, 2, 1>,
            cudaFuncAttributeMaxDynamicSharedMemorySize, SMEM1);
        attr_done = true;
    }

    // ---- prepass ----
    init_max<<<cdiv(B_ * CN, 256), 256>>>();
    {
        size_t tot = (size_t)CN * TP2;
        split_pack<<<(int)cdiv((int)tot, 256), 256>>>(W2, W2h, W2l, CN, T_, TP2);
    }
    {
        size_t tot = (size_t)B_ * T_ * HP2;
        pack_hi<<<(int)((tot + 255) / 256), 256>>>(H, Hh, B_ * T_, HD, HP2);
    }
    split_transpose<<<dim3(TP / 32, cdiv(XD, 32), B_), dim3(32, 8)>>>(
        X, (size_t)T_ * XD, Xth, Xtl, (size_t)XD * TP2, T_, XD, TP2);
    split_transpose<<<dim3(XD / 32, cdiv(HD, 32), 1), dim3(32, 8)>>>(
        W1, 0, W1th, W1tl, 0, XD, HD, XP2);

    // 1) Z partials = W2 @ X[b], k-split x2 (3-product split, fp32 out)
    gemm_bf16s<96, 0, 3><<<dim3(cdiv(CN, 128), 2, B_), 256, SMEM3>>>(
        W2h, W2l, 0, Xth, Xtl, (size_t)XD * TP2,
        (uint32_t*)Zp, nullptr, nullptr, (size_t)CN * XD, CN, XD, TP, 1.0f);

    // 1b) Z = split(Zp0 + Zp1)
    {
        size_t tot = (size_t)B_ * CN * XP2;
        combine_split<<<(int)((tot + 255) / 256), 256>>>();
    }

    // 2) Y[b] = Z[b] @ W1    (3-product split, split output)
    gemm_bf16s<96, 1, 3><<<dim3(cdiv(CN, 128), cdiv(HD, 96), B_), 256, SMEM3>>>(
        Zh, Zl, (size_t)CN * XP2, W1th, W1tl, 0,
        Yh, Yl, nullptr, (size_t)CN * HP2, CN, HD, XD, 1.0f);

    // 3) Lb[b] = bf16(scale * Y[b] @ H[b]^T)  (single product, bf16 out + max)
    gemm_bf16s<96, 2, 1><<<dim3(cdiv(CN, 128), cdiv(T_, 96), B_), 256, SMEM1>>>(
        Yh, Yh, (size_t)CN * HP2, Hh, Hh, (size_t)T_ * HP2,
        Lb, nullptr, Mx, (size_t)CN * T2, CN, T_, HD, scale);

    // 4+5) candidate scan + exact recompute + gather -> out
    softmax_gather<<<dim3(CN, B_), 256>>>(H, out);
}